// round 10
// baseline (speedup 1.0000x reference)
#include <cuda_runtime.h>
#include <cuda_bf16.h>
#include <cuda_fp16.h>
#include <cstdint>

#define M_NODES 50000
#define M_PAD   50048          // 391 * 128
#define K_NBR   32
#define DCH     256

__device__ __half         g_hh[M_NODES * DCH];   // h stored fp16
__device__ __nv_bfloat16  g_xhi[M_PAD * DCH];
__device__ __nv_bfloat16  g_xlo[M_PAD * DCH];
__device__ __nv_bfloat16  g_whi[DCH * DCH];
__device__ __nv_bfloat16  g_wlo[DCH * DCH];

#define XBLOCKS (M_PAD * DCH / 4 / 256)      // 12512
#define WBLOCKS (DCH * DCH / 4 / 256)        // 64

// ===================== split fp32 -> (hi, lo) bf16 ==========================
__global__ void __launch_bounds__(256) convert_xw(const float* __restrict__ x,
                                                  const float* __restrict__ w) {
    if (blockIdx.x < XBLOCKS) {
        size_t i4 = (size_t)blockIdx.x * 256 + threadIdx.x;
        float4 f = make_float4(0.f, 0.f, 0.f, 0.f);
        if (i4 * 4 < (size_t)M_NODES * DCH)
            f = *reinterpret_cast<const float4*>(x + i4 * 4);
        __nv_bfloat162 h01 = __floats2bfloat162_rn(f.x, f.y);
        __nv_bfloat162 h23 = __floats2bfloat162_rn(f.z, f.w);
        __nv_bfloat162 l01 = __floats2bfloat162_rn(f.x - __bfloat162float(h01.x),
                                                   f.y - __bfloat162float(h01.y));
        __nv_bfloat162 l23 = __floats2bfloat162_rn(f.z - __bfloat162float(h23.x),
                                                   f.w - __bfloat162float(h23.y));
        reinterpret_cast<uint2*>(g_xhi)[i4] =
            make_uint2(*reinterpret_cast<uint32_t*>(&h01), *reinterpret_cast<uint32_t*>(&h23));
        reinterpret_cast<uint2*>(g_xlo)[i4] =
            make_uint2(*reinterpret_cast<uint32_t*>(&l01), *reinterpret_cast<uint32_t*>(&l23));
    } else {
        size_t i4 = (size_t)(blockIdx.x - XBLOCKS) * 256 + threadIdx.x;
        float4 f = *reinterpret_cast<const float4*>(w + i4 * 4);
        __nv_bfloat162 h01 = __floats2bfloat162_rn(f.x, f.y);
        __nv_bfloat162 h23 = __floats2bfloat162_rn(f.z, f.w);
        __nv_bfloat162 l01 = __floats2bfloat162_rn(f.x - __bfloat162float(h01.x),
                                                   f.y - __bfloat162float(h01.y));
        __nv_bfloat162 l23 = __floats2bfloat162_rn(f.z - __bfloat162float(h23.x),
                                                   f.w - __bfloat162float(h23.y));
        reinterpret_cast<uint2*>(g_whi)[i4] =
            make_uint2(*reinterpret_cast<uint32_t*>(&h01), *reinterpret_cast<uint32_t*>(&h23));
        reinterpret_cast<uint2*>(g_wlo)[i4] =
            make_uint2(*reinterpret_cast<uint32_t*>(&l01), *reinterpret_cast<uint32_t*>(&l23));
    }
}

// ===================== mma.sync bf16 split GEMM, BM=128 BN=256 ===============
// h = x_hi*W_hi (kt 0-7) + x_hi*W_lo (8-15) + x_lo*W_hi (16-23), BK=32.
// 512 threads, 16 warps (4m x 4n), warp tile 32x64 (proven addressing).
// cp.async 3-stage pipeline; x pre-split so no conversion in the hot loop.
#define AS_LD    40                    // bf16 per smem row (32 data + 8 pad) = 80B
#define A_STAGE  (128 * AS_LD * 2)     // 10240 B
#define B_STAGE  (256 * AS_LD * 2)     // 20480 B
#define NSTAGE   3
#define GEMM_SMEM (NSTAGE * (A_STAGE + B_STAGE))   // 92160

__device__ __forceinline__ uint32_t smem_u32(const void* p) {
    uint32_t a;
    asm("{ .reg .u64 t; cvta.to.shared.u64 t, %1; cvt.u32.u64 %0, t; }" : "=r"(a) : "l"(p));
    return a;
}
__device__ __forceinline__ void cp16(uint32_t s, const void* g) {
    asm volatile("cp.async.cg.shared.global [%0], [%1], 16;" :: "r"(s), "l"(g));
}
__device__ __forceinline__ void ldsm_x4(uint32_t* r, uint32_t addr) {
    asm volatile("ldmatrix.sync.aligned.m8n8.x4.shared.b16 {%0,%1,%2,%3}, [%4];"
                 : "=r"(r[0]), "=r"(r[1]), "=r"(r[2]), "=r"(r[3]) : "r"(addr));
}
__device__ __forceinline__ void ldsm_x2(uint32_t* r, uint32_t addr) {
    asm volatile("ldmatrix.sync.aligned.m8n8.x2.shared.b16 {%0,%1}, [%2];"
                 : "=r"(r[0]), "=r"(r[1]) : "r"(addr));
}
__device__ __forceinline__ void mma_bf16(float* d, const uint32_t* a, const uint32_t* b) {
    asm volatile(
        "mma.sync.aligned.m16n8k16.row.col.f32.bf16.bf16.f32 "
        "{%0,%1,%2,%3}, {%4,%5,%6,%7}, {%8,%9}, {%0,%1,%2,%3};"
        : "+f"(d[0]), "+f"(d[1]), "+f"(d[2]), "+f"(d[3])
        : "r"(a[0]), "r"(a[1]), "r"(a[2]), "r"(a[3]), "r"(b[0]), "r"(b[1]));
}

__global__ void __launch_bounds__(512) gemm_mma() {
    extern __shared__ char smem[];
    const uint32_t sA0 = smem_u32(smem);
    const uint32_t sB0 = sA0 + NSTAGE * A_STAGE;

    const int tid  = threadIdx.x;
    const int bm   = blockIdx.x * 128;
    const int warp = tid >> 5, lane = tid & 31;
    const int mw   = warp >> 2, nw = warp & 3;       // 4m x 4n warps

    float acc[2][8][4];
#pragma unroll
    for (int mt = 0; mt < 2; mt++)
#pragma unroll
        for (int nt = 0; nt < 8; nt++)
#pragma unroll
            for (int q = 0; q < 4; q++) acc[mt][nt][q] = 0.0f;

    auto issue = [&](int kt) {
        const int stage = kt % NSTAGE;
        const __nv_bfloat16* asrc = (kt < 16) ? g_xhi : g_xlo;
        const __nv_bfloat16* bsrc = (kt >= 8 && kt < 16) ? g_wlo : g_whi;
        const int kcol = (kt & 7) * 32;
        // A: 128 rows x 64B = 512 chunks (1/thread)
        {
            int r = tid >> 2, j = tid & 3;
            cp16(sA0 + stage * A_STAGE + r * 80 + j * 16,
                 asrc + (size_t)(bm + r) * DCH + kcol + j * 8);
        }
        // B: 256 rows x 64B = 1024 chunks (2/thread)
#pragma unroll
        for (int l = 0; l < 2; l++) {
            int c = tid + l * 512, r = c >> 2, j = c & 3;
            cp16(sB0 + stage * B_STAGE + r * 80 + j * 16,
                 bsrc + (size_t)r * DCH + kcol + j * 8);
        }
        asm volatile("cp.async.commit_group;" ::: "memory");
    };

    auto compute = [&](int stage) {
        const uint32_t as_b = sA0 + stage * A_STAGE;
        const uint32_t bs_b = sB0 + stage * B_STAGE;
#pragma unroll
        for (int ks = 0; ks < 2; ks++) {
            const int k0 = ks * 16;
            uint32_t afrag[2][4];
#pragma unroll
            for (int mt = 0; mt < 2; mt++)
                ldsm_x4(afrag[mt], as_b + 2u * ((mw * 32 + mt * 16 + (lane & 15)) * AS_LD +
                                                (lane >> 4) * 8 + k0));
            uint32_t bfrag[8][2];
#pragma unroll
            for (int nt = 0; nt < 8; nt++)
                ldsm_x2(bfrag[nt], bs_b + 2u * ((nw * 64 + nt * 8 + (lane & 7)) * AS_LD +
                                                ((lane >> 3) & 1) * 8 + k0));
#pragma unroll
            for (int mt = 0; mt < 2; mt++)
#pragma unroll
                for (int nt = 0; nt < 8; nt++)
                    mma_bf16(acc[mt][nt], afrag[mt], bfrag[nt]);
        }
    };

    issue(0);
    issue(1);

#pragma unroll 1
    for (int kt = 0; kt < 24; kt++) {
        if (kt < 23)
            asm volatile("cp.async.wait_group 1;" ::: "memory");
        else
            asm volatile("cp.async.wait_group 0;" ::: "memory");
        __syncthreads();
        if (kt + 2 < 24) issue(kt + 2);
        compute(kt % NSTAGE);
    }

    // epilogue: acc -> g_hh (fp16 packed pairs)
#pragma unroll
    for (int mt = 0; mt < 2; mt++) {
        const int m0 = bm + mw * 32 + mt * 16 + (lane >> 2);
#pragma unroll
        for (int nt = 0; nt < 8; nt++) {
            const int n = nw * 64 + nt * 8 + (lane & 3) * 2;
            __half2 p01 = __floats2half2_rn(acc[mt][nt][0], acc[mt][nt][1]);
            __half2 p23 = __floats2half2_rn(acc[mt][nt][2], acc[mt][nt][3]);
            if (m0 < M_NODES)
                *reinterpret_cast<__half2*>(&g_hh[(size_t)m0 * DCH + n]) = p01;
            if (m0 + 8 < M_NODES)
                *reinterpret_cast<__half2*>(&g_hh[(size_t)(m0 + 8) * DCH + n]) = p23;
        }
    }
}

// ===================== gather: f16x2 packed 2-channel selection (R9) =========
#define CE2H(a, b) { __half2 _mn = __hmin2(v[a], v[b]); \
                     __half2 _mx = __hmax2(v[a], v[b]); \
                     v[a] = _mn; v[b] = _mx; }

#define OEMS16(o, C) \
    C(o+0,o+1)  C(o+2,o+3)   C(o+4,o+5)   C(o+6,o+7) \
    C(o+8,o+9)  C(o+10,o+11) C(o+12,o+13) C(o+14,o+15) \
    C(o+0,o+2)  C(o+1,o+3)   C(o+4,o+6)   C(o+5,o+7) \
    C(o+8,o+10) C(o+9,o+11)  C(o+12,o+14) C(o+13,o+15) \
    C(o+1,o+2)  C(o+5,o+6)   C(o+9,o+10)  C(o+13,o+14) \
    C(o+0,o+4)  C(o+1,o+5)   C(o+2,o+6)   C(o+3,o+7) \
    C(o+8,o+12) C(o+9,o+13)  C(o+10,o+14) C(o+11,o+15) \
    C(o+2,o+4)  C(o+3,o+5)   C(o+10,o+12) C(o+11,o+13) \
    C(o+1,o+2)  C(o+3,o+4)   C(o+5,o+6) \
    C(o+9,o+10) C(o+11,o+12) C(o+13,o+14) \
    C(o+0,o+8)  C(o+1,o+9)   C(o+2,o+10)  C(o+3,o+11) \
    C(o+4,o+12) C(o+5,o+13)  C(o+6,o+14)  C(o+7,o+15) \
    C(o+4,o+8)  C(o+5,o+9)   C(o+6,o+10)  C(o+7,o+11) \
    C(o+2,o+4)  C(o+3,o+5)   C(o+6,o+8) \
    C(o+7,o+9)  C(o+10,o+12) C(o+11,o+13) \
    C(o+1,o+2)  C(o+3,o+4)   C(o+5,o+6)   C(o+7,o+8) \
    C(o+9,o+10) C(o+11,o+12) C(o+13,o+14)

__global__ void __launch_bounds__(128) gather_trim(
    const void* __restrict__ nbrs_raw,
    float* __restrict__ out)
{
    __shared__ int sn[K_NBR];

    const int node = blockIdx.x;
    const int tid  = threadIdx.x;

    if (tid < K_NBR) {
        const int* w = reinterpret_cast<const int*>(nbrs_raw);
        unsigned m = __ballot_sync(0xffffffffu, w[2 * tid + 1] == 0);
        bool is64 = (m == 0xffffffffu);
        long long idx = is64
            ? reinterpret_cast<const long long*>(nbrs_raw)[(size_t)node * K_NBR + tid]
            : (long long)reinterpret_cast<const int*>(nbrs_raw)[(size_t)node * K_NBR + tid];
        sn[tid] = (int)idx * DCH;
    }
    __syncthreads();

    __half2 v[K_NBR];
#pragma unroll
    for (int k = 0; k < K_NBR; k++)
        v[k] = *reinterpret_cast<const __half2*>(&g_hh[sn[k] + 2 * tid]);

    OEMS16(0, CE2H)
    OEMS16(16, CE2H)

#pragma unroll
    for (int i = 0; i < 16; i++) {
        __half2 a = v[i], b = v[31 - i];
        v[i]      = __hmin2(a, b);
        v[31 - i] = __hmax2(a, b);
    }
#pragma unroll
    for (int j = 8; j >= 2; j >>= 1)
#pragma unroll
        for (int i = 0; i < j; i++)
            v[i] = __hmax2(v[i], v[i + j]);
#pragma unroll
    for (int j = 8; j >= 2; j >>= 1)
#pragma unroll
        for (int i = 0; i < j; i++)
            v[16 + i] = __hmin2(v[16 + i], v[16 + i + j]);

    float2 f0 = __half22float2(v[0]);
    float2 f1 = __half22float2(v[1]);
    float2 f2 = __half22float2(v[16]);
    float2 f3 = __half22float2(v[17]);
    float2 r  = make_float2((f0.x + f1.x + f2.x + f3.x) * 0.25f,
                            (f0.y + f1.y + f2.y + f3.y) * 0.25f);

    *reinterpret_cast<float2*>(&out[(size_t)node * DCH + 2 * tid]) = r;
}

// ===================== launch ===============================================
extern "C" void kernel_launch(void* const* d_in, const int* in_sizes, int n_in,
                              void* d_out, int out_size)
{
    const float* x    = nullptr;
    const void*  nbrs = nullptr;
    const float* W    = nullptr;

    for (int i = 0; i < n_in; i++) {
        if      (in_sizes[i] == M_NODES * DCH)   x    = (const float*)d_in[i];
        else if (in_sizes[i] == M_NODES * K_NBR) nbrs = d_in[i];
        else if (in_sizes[i] == DCH * DCH)       W    = (const float*)d_in[i];
    }
    if (!x)    x    = (const float*)d_in[0];
    if (!nbrs) nbrs = d_in[1];
    if (!W)    W    = (const float*)d_in[2];

    cudaFuncSetAttribute(gemm_mma, cudaFuncAttributeMaxDynamicSharedMemorySize, GEMM_SMEM);

    convert_xw<<<XBLOCKS + WBLOCKS, 256>>>(x, W);

    gemm_mma<<<M_PAD / 128, 512, GEMM_SMEM>>>();

    gather_trim<<<M_NODES, 128>>>(nbrs, (float*)d_out);
}

// round 11
// speedup vs baseline: 1.0747x; 1.0747x over previous
#include <cuda_runtime.h>
#include <cuda_bf16.h>
#include <cuda_fp16.h>
#include <cstdint>

#define M_NODES 50000
#define K_NBR   32
#define DCH     256

__device__ __half         g_hh[M_NODES * DCH];   // h stored fp16
__device__ __nv_bfloat16  g_whi[DCH * DCH];
__device__ __nv_bfloat16  g_wlo[DCH * DCH];

// ===================== W split (tiny) ========================================
__global__ void __launch_bounds__(256) convert_w(const float* __restrict__ w) {
    size_t i4 = (size_t)blockIdx.x * 256 + threadIdx.x;
    if (i4 * 4 >= (size_t)DCH * DCH) return;
    float4 f = *reinterpret_cast<const float4*>(w + i4 * 4);
    __nv_bfloat162 h01 = __floats2bfloat162_rn(f.x, f.y);
    __nv_bfloat162 h23 = __floats2bfloat162_rn(f.z, f.w);
    __nv_bfloat162 l01 = __floats2bfloat162_rn(f.x - __bfloat162float(h01.x),
                                               f.y - __bfloat162float(h01.y));
    __nv_bfloat162 l23 = __floats2bfloat162_rn(f.z - __bfloat162float(h23.x),
                                               f.w - __bfloat162float(h23.y));
    reinterpret_cast<uint2*>(g_whi)[i4] =
        make_uint2(*reinterpret_cast<uint32_t*>(&h01), *reinterpret_cast<uint32_t*>(&h23));
    reinterpret_cast<uint2*>(g_wlo)[i4] =
        make_uint2(*reinterpret_cast<uint32_t*>(&l01), *reinterpret_cast<uint32_t*>(&l23));
}

// ===================== mma.sync bf16 split GEMM (R9 proven form) =============
#define AS_LD 40

__device__ __forceinline__ uint32_t smem_u32(const void* p) {
    uint32_t a;
    asm("{ .reg .u64 t; cvta.to.shared.u64 t, %1; cvt.u32.u64 %0, t; }" : "=r"(a) : "l"(p));
    return a;
}
__device__ __forceinline__ void ldsm_x4(uint32_t* r, uint32_t addr) {
    asm volatile("ldmatrix.sync.aligned.m8n8.x4.shared.b16 {%0,%1,%2,%3}, [%4];"
                 : "=r"(r[0]), "=r"(r[1]), "=r"(r[2]), "=r"(r[3]) : "r"(addr));
}
__device__ __forceinline__ void ldsm_x2(uint32_t* r, uint32_t addr) {
    asm volatile("ldmatrix.sync.aligned.m8n8.x2.shared.b16 {%0,%1}, [%2];"
                 : "=r"(r[0]), "=r"(r[1]) : "r"(addr));
}
__device__ __forceinline__ void mma_bf16(float* d, const uint32_t* a, const uint32_t* b) {
    asm volatile(
        "mma.sync.aligned.m16n8k16.row.col.f32.bf16.bf16.f32 "
        "{%0,%1,%2,%3}, {%4,%5,%6,%7}, {%8,%9}, {%0,%1,%2,%3};"
        : "+f"(d[0]), "+f"(d[1]), "+f"(d[2]), "+f"(d[3])
        : "r"(a[0]), "r"(a[1]), "r"(a[2]), "r"(a[3]), "r"(b[0]), "r"(b[1]));
}

__global__ void __launch_bounds__(256) gemm_mma(const float* __restrict__ x) {
    __shared__ __align__(16) __nv_bfloat16 As[2][128 * AS_LD];
    __shared__ __align__(16) __nv_bfloat16 Bs[2][128 * AS_LD];

    const int tid  = threadIdx.x;
    const int bm   = blockIdx.x * 128;
    const int bn   = blockIdx.y * 128;
    const int warp = tid >> 5, lane = tid & 31;
    const int mw   = warp >> 1, nw = warp & 1;

    float acc[2][8][4];
#pragma unroll
    for (int mt = 0; mt < 2; mt++)
#pragma unroll
        for (int nt = 0; nt < 8; nt++)
#pragma unroll
            for (int q = 0; q < 4; q++) acc[mt][nt][q] = 0.0f;

    float4 ar[4];
    uint2  br[4];

    auto load_g = [&](int kt) {
        const int seg = kt >> 3;
        const int kk  = (kt & 7) * 32;
        const __nv_bfloat16* wsrc = (seg == 1) ? g_wlo : g_whi;
#pragma unroll
        for (int l = 0; l < 4; l++) {
            int t = tid + l * 256, r = t >> 3, j = t & 7;
            int row = bm + r;
            float4 v = make_float4(0.f, 0.f, 0.f, 0.f);
            if (row < M_NODES)
                v = *reinterpret_cast<const float4*>(x + (size_t)row * DCH + kk + j * 4);
            ar[l] = v;
            br[l] = *reinterpret_cast<const uint2*>(wsrc + (size_t)(bn + r) * DCH + kk + j * 4);
        }
    };

    auto sts = [&](int kt, int buf) {
        const bool hi = ((kt >> 3) < 2);
#pragma unroll
        for (int l = 0; l < 4; l++) {
            int t = tid + l * 256, r = t >> 3, j = t & 7;
            float4 v = ar[l];
            __nv_bfloat162 h01 = __floats2bfloat162_rn(v.x, v.y);
            __nv_bfloat162 h23 = __floats2bfloat162_rn(v.z, v.w);
            __nv_bfloat162 p0, p1;
            if (hi) { p0 = h01; p1 = h23; }
            else {
                p0 = __floats2bfloat162_rn(v.x - __bfloat162float(h01.x),
                                           v.y - __bfloat162float(h01.y));
                p1 = __floats2bfloat162_rn(v.z - __bfloat162float(h23.x),
                                           v.w - __bfloat162float(h23.y));
            }
            *reinterpret_cast<uint2*>(&As[buf][r * AS_LD + j * 4]) =
                make_uint2(*reinterpret_cast<uint32_t*>(&p0), *reinterpret_cast<uint32_t*>(&p1));
            *reinterpret_cast<uint2*>(&Bs[buf][r * AS_LD + j * 4]) = br[l];
        }
    };

    auto compute = [&](int buf) {
        const uint32_t as_b = smem_u32(&As[buf][0]);
        const uint32_t bs_b = smem_u32(&Bs[buf][0]);
#pragma unroll
        for (int ks = 0; ks < 2; ks++) {
            const int k0 = ks * 16;
            uint32_t afrag[2][4];
#pragma unroll
            for (int mt = 0; mt < 2; mt++)
                ldsm_x4(afrag[mt], as_b + 2u * ((mw * 32 + mt * 16 + (lane & 15)) * AS_LD +
                                                (lane >> 4) * 8 + k0));
            uint32_t bfrag[8][2];
#pragma unroll
            for (int nt = 0; nt < 8; nt++)
                ldsm_x2(bfrag[nt], bs_b + 2u * ((nw * 64 + nt * 8 + (lane & 7)) * AS_LD +
                                                ((lane >> 3) & 1) * 8 + k0));
#pragma unroll
            for (int mt = 0; mt < 2; mt++)
#pragma unroll
                for (int nt = 0; nt < 8; nt++)
                    mma_bf16(acc[mt][nt], afrag[mt], bfrag[nt]);
        }
    };

    load_g(0);
    sts(0, 0);
    __syncthreads();

#pragma unroll 1
    for (int kt = 0; kt < 24; kt++) {
        const int buf = kt & 1;
        if (kt < 23) load_g(kt + 1);
        compute(buf);
        if (kt < 23) sts(kt + 1, buf ^ 1);
        __syncthreads();
    }

    // epilogue: acc -> g_hh (fp16 packed pairs)
#pragma unroll
    for (int mt = 0; mt < 2; mt++) {
        const int m0 = bm + mw * 32 + mt * 16 + (lane >> 2);
#pragma unroll
        for (int nt = 0; nt < 8; nt++) {
            const int n = bn + nw * 64 + nt * 8 + (lane & 3) * 2;
            __half2 p01 = __floats2half2_rn(acc[mt][nt][0], acc[mt][nt][1]);
            __half2 p23 = __floats2half2_rn(acc[mt][nt][2], acc[mt][nt][3]);
            if (m0 < M_NODES)
                *reinterpret_cast<__half2*>(&g_hh[(size_t)m0 * DCH + n]) = p01;
            if (m0 + 8 < M_NODES)
                *reinterpret_cast<__half2*>(&g_hh[(size_t)(m0 + 8) * DCH + n]) = p23;
        }
    }
}

// ===================== gather: 4 channels/thread, 2 nodes/block ==============
// Thread owns channels [4t64..4t64+3] of node (2*blockIdx + (tid>>6)) as two
// half2 arrays. Warp load per neighbor = LDG.64 (256B coalesced, 2 lines).
// Two independent networks per thread -> ILP fills the alu rt=2 slots.
#define CE2(arr, a, b) { __half2 _mn = __hmin2(arr[a], arr[b]); \
                         __half2 _mx = __hmax2(arr[a], arr[b]); \
                         arr[a] = _mn; arr[b] = _mx; }

// Batcher odd-even mergesort-16, ascending, 63 comparators (literal indices)
#define OEMS16(arr, o) \
    CE2(arr,o+0,o+1)  CE2(arr,o+2,o+3)   CE2(arr,o+4,o+5)   CE2(arr,o+6,o+7) \
    CE2(arr,o+8,o+9)  CE2(arr,o+10,o+11) CE2(arr,o+12,o+13) CE2(arr,o+14,o+15) \
    CE2(arr,o+0,o+2)  CE2(arr,o+1,o+3)   CE2(arr,o+4,o+6)   CE2(arr,o+5,o+7) \
    CE2(arr,o+8,o+10) CE2(arr,o+9,o+11)  CE2(arr,o+12,o+14) CE2(arr,o+13,o+15) \
    CE2(arr,o+1,o+2)  CE2(arr,o+5,o+6)   CE2(arr,o+9,o+10)  CE2(arr,o+13,o+14) \
    CE2(arr,o+0,o+4)  CE2(arr,o+1,o+5)   CE2(arr,o+2,o+6)   CE2(arr,o+3,o+7) \
    CE2(arr,o+8,o+12) CE2(arr,o+9,o+13)  CE2(arr,o+10,o+14) CE2(arr,o+11,o+15) \
    CE2(arr,o+2,o+4)  CE2(arr,o+3,o+5)   CE2(arr,o+10,o+12) CE2(arr,o+11,o+13) \
    CE2(arr,o+1,o+2)  CE2(arr,o+3,o+4)   CE2(arr,o+5,o+6) \
    CE2(arr,o+9,o+10) CE2(arr,o+11,o+12) CE2(arr,o+13,o+14) \
    CE2(arr,o+0,o+8)  CE2(arr,o+1,o+9)   CE2(arr,o+2,o+10)  CE2(arr,o+3,o+11) \
    CE2(arr,o+4,o+12) CE2(arr,o+5,o+13)  CE2(arr,o+6,o+14)  CE2(arr,o+7,o+15) \
    CE2(arr,o+4,o+8)  CE2(arr,o+5,o+9)   CE2(arr,o+6,o+10)  CE2(arr,o+7,o+11) \
    CE2(arr,o+2,o+4)  CE2(arr,o+3,o+5)   CE2(arr,o+6,o+8) \
    CE2(arr,o+7,o+9)  CE2(arr,o+10,o+12) CE2(arr,o+11,o+13) \
    CE2(arr,o+1,o+2)  CE2(arr,o+3,o+4)   CE2(arr,o+5,o+6)   CE2(arr,o+7,o+8) \
    CE2(arr,o+9,o+10) CE2(arr,o+11,o+12) CE2(arr,o+13,o+14)

// full selection on one half2 array: ranks 14,15 -> arr[0],arr[1];
// ranks 16,17 -> arr[16],arr[17]
#define SELECT32(arr) \
    OEMS16(arr, 0) \
    OEMS16(arr, 16) \
    _Pragma("unroll") \
    for (int i = 0; i < 16; i++) { \
        __half2 _a = arr[i], _b = arr[31 - i]; \
        arr[i]      = __hmin2(_a, _b); \
        arr[31 - i] = __hmax2(_a, _b); \
    } \
    _Pragma("unroll") \
    for (int j = 8; j >= 2; j >>= 1) \
        _Pragma("unroll") \
        for (int i = 0; i < j; i++) \
            arr[i] = __hmax2(arr[i], arr[i + j]); \
    _Pragma("unroll") \
    for (int j = 8; j >= 2; j >>= 1) \
        _Pragma("unroll") \
        for (int i = 0; i < j; i++) \
            arr[16 + i] = __hmin2(arr[16 + i], arr[16 + i + j]);

__global__ void __launch_bounds__(128) gather_trim(
    const void* __restrict__ nbrs_raw,
    float* __restrict__ out)
{
    __shared__ int sn[2][K_NBR];   // row offsets for the block's 2 nodes

    const int tid   = threadIdx.x;
    const int half  = tid >> 6;                 // which node in this block
    const int t64   = tid & 63;
    const int node  = blockIdx.x * 2 + half;

    if (tid < 2 * K_NBR) {
        const int  h = tid >> 5;                // node-half this thread fills
        const int  k = tid & 31;
        const int* w = reinterpret_cast<const int*>(nbrs_raw);
        unsigned m = __ballot_sync(0xffffffffu, w[2 * (tid & 31) + 1] == 0);
        bool is64 = (m == 0xffffffffu);
        long long nd = (long long)blockIdx.x * 2 + h;
        long long idx = is64
            ? reinterpret_cast<const long long*>(nbrs_raw)[nd * K_NBR + k]
            : (long long)reinterpret_cast<const int*>(nbrs_raw)[nd * K_NBR + k];
        sn[h][k] = (int)idx * DCH;
    }
    __syncthreads();

    // thread owns channels 4*t64 .. 4*t64+3 of its node (one uint2 per nbr)
    __half2 va[K_NBR], vb[K_NBR];
#pragma unroll
    for (int k = 0; k < K_NBR; k++) {
        uint2 u = *reinterpret_cast<const uint2*>(&g_hh[sn[half][k] + 4 * t64]);
        va[k] = *reinterpret_cast<__half2*>(&u.x);
        vb[k] = *reinterpret_cast<__half2*>(&u.y);
    }

    SELECT32(va)
    SELECT32(vb)

    float2 a0 = __half22float2(va[0]),  a1 = __half22float2(va[1]);
    float2 a2 = __half22float2(va[16]), a3 = __half22float2(va[17]);
    float2 b0 = __half22float2(vb[0]),  b1 = __half22float2(vb[1]);
    float2 b2 = __half22float2(vb[16]), b3 = __half22float2(vb[17]);

    float4 r = make_float4((a0.x + a1.x + a2.x + a3.x) * 0.25f,
                           (a0.y + a1.y + a2.y + a3.y) * 0.25f,
                           (b0.x + b1.x + b2.x + b3.x) * 0.25f,
                           (b0.y + b1.y + b2.y + b3.y) * 0.25f);

    *reinterpret_cast<float4*>(&out[(size_t)node * DCH + 4 * t64]) = r;
}

// ===================== launch ===============================================
extern "C" void kernel_launch(void* const* d_in, const int* in_sizes, int n_in,
                              void* d_out, int out_size)
{
    const float* x    = nullptr;
    const void*  nbrs = nullptr;
    const float* W    = nullptr;

    for (int i = 0; i < n_in; i++) {
        if      (in_sizes[i] == M_NODES * DCH)   x    = (const float*)d_in[i];
        else if (in_sizes[i] == M_NODES * K_NBR) nbrs = d_in[i];
        else if (in_sizes[i] == DCH * DCH)       W    = (const float*)d_in[i];
    }
    if (!x)    x    = (const float*)d_in[0];
    if (!nbrs) nbrs = d_in[1];
    if (!W)    W    = (const float*)d_in[2];

    convert_w<<<(DCH * DCH / 4 + 255) / 256, 256>>>(W);

    dim3 ggrid((M_NODES + 127) / 128, 2);
    gemm_mma<<<ggrid, 256>>>(x);

    gather_trim<<<M_NODES / 2, 128>>>(nbrs, (float*)d_out);
}

// round 12
// speedup vs baseline: 1.4149x; 1.3165x over previous
#include <cuda_runtime.h>
#include <cuda_fp16.h>
#include <cstdint>

#define M_NODES 50000
#define K_NBR   32
#define DCH     256

__device__ __half g_hh[M_NODES * DCH];   // h stored fp16
__device__ __half g_wh[DCH * DCH];       // W in fp16

// ===================== W -> fp16 (tiny) ======================================
__global__ void __launch_bounds__(256) convert_w(const float* __restrict__ w) {
    size_t i4 = (size_t)blockIdx.x * 256 + threadIdx.x;
    if (i4 * 4 >= (size_t)DCH * DCH) return;
    float4 f = *reinterpret_cast<const float4*>(w + i4 * 4);
    __half2 p01 = __floats2half2_rn(f.x, f.y);
    __half2 p23 = __floats2half2_rn(f.z, f.w);
    reinterpret_cast<uint2*>(g_wh)[i4] =
        make_uint2(*reinterpret_cast<uint32_t*>(&p01), *reinterpret_cast<uint32_t*>(&p23));
}

// ===================== mma.sync fp16 GEMM, single K=256 pass =================
// Block 128x128, 8 warps (4m x 2n), warp tile 32x64, BK=32, double-buffered,
// x converted fp32->fp16 in registers on the fly (R9-proven structure).
#define AS_LD 40   // halves per smem row (32 data + 8 pad) -> 80B stride

__device__ __forceinline__ uint32_t smem_u32(const void* p) {
    uint32_t a;
    asm("{ .reg .u64 t; cvta.to.shared.u64 t, %1; cvt.u32.u64 %0, t; }" : "=r"(a) : "l"(p));
    return a;
}
__device__ __forceinline__ void ldsm_x4(uint32_t* r, uint32_t addr) {
    asm volatile("ldmatrix.sync.aligned.m8n8.x4.shared.b16 {%0,%1,%2,%3}, [%4];"
                 : "=r"(r[0]), "=r"(r[1]), "=r"(r[2]), "=r"(r[3]) : "r"(addr));
}
__device__ __forceinline__ void ldsm_x2(uint32_t* r, uint32_t addr) {
    asm volatile("ldmatrix.sync.aligned.m8n8.x2.shared.b16 {%0,%1}, [%2];"
                 : "=r"(r[0]), "=r"(r[1]) : "r"(addr));
}
__device__ __forceinline__ void mma_f16(float* d, const uint32_t* a, const uint32_t* b) {
    asm volatile(
        "mma.sync.aligned.m16n8k16.row.col.f32.f16.f16.f32 "
        "{%0,%1,%2,%3}, {%4,%5,%6,%7}, {%8,%9}, {%0,%1,%2,%3};"
        : "+f"(d[0]), "+f"(d[1]), "+f"(d[2]), "+f"(d[3])
        : "r"(a[0]), "r"(a[1]), "r"(a[2]), "r"(a[3]), "r"(b[0]), "r"(b[1]));
}

__global__ void __launch_bounds__(256) gemm_mma(const float* __restrict__ x) {
    __shared__ __align__(16) __half As[2][128 * AS_LD];
    __shared__ __align__(16) __half Bs[2][128 * AS_LD];

    const int tid  = threadIdx.x;
    const int bm   = blockIdx.x * 128;
    const int bn   = blockIdx.y * 128;
    const int warp = tid >> 5, lane = tid & 31;
    const int mw   = warp >> 1, nw = warp & 1;

    float acc[2][8][4];
#pragma unroll
    for (int mt = 0; mt < 2; mt++)
#pragma unroll
        for (int nt = 0; nt < 8; nt++)
#pragma unroll
            for (int q = 0; q < 4; q++) acc[mt][nt][q] = 0.0f;

    float4 ar[4];
    uint2  br[4];

    auto load_g = [&](int kt) {
        const int kk = kt * 32;
#pragma unroll
        for (int l = 0; l < 4; l++) {
            int t = tid + l * 256, r = t >> 3, j = t & 7;
            int row = bm + r;
            float4 v = make_float4(0.f, 0.f, 0.f, 0.f);
            if (row < M_NODES)
                v = *reinterpret_cast<const float4*>(x + (size_t)row * DCH + kk + j * 4);
            ar[l] = v;
            br[l] = *reinterpret_cast<const uint2*>(g_wh + (size_t)(bn + r) * DCH + kk + j * 4);
        }
    };

    auto sts = [&](int buf) {
#pragma unroll
        for (int l = 0; l < 4; l++) {
            int t = tid + l * 256, r = t >> 3, j = t & 7;
            float4 v = ar[l];
            __half2 p0 = __floats2half2_rn(v.x, v.y);
            __half2 p1 = __floats2half2_rn(v.z, v.w);
            *reinterpret_cast<uint2*>(&As[buf][r * AS_LD + j * 4]) =
                make_uint2(*reinterpret_cast<uint32_t*>(&p0), *reinterpret_cast<uint32_t*>(&p1));
            *reinterpret_cast<uint2*>(&Bs[buf][r * AS_LD + j * 4]) = br[l];
        }
    };

    auto compute = [&](int buf) {
        const uint32_t as_b = smem_u32(&As[buf][0]);
        const uint32_t bs_b = smem_u32(&Bs[buf][0]);
#pragma unroll
        for (int ks = 0; ks < 2; ks++) {
            const int k0 = ks * 16;
            uint32_t afrag[2][4];
#pragma unroll
            for (int mt = 0; mt < 2; mt++)
                ldsm_x4(afrag[mt], as_b + 2u * ((mw * 32 + mt * 16 + (lane & 15)) * AS_LD +
                                                (lane >> 4) * 8 + k0));
            uint32_t bfrag[8][2];
#pragma unroll
            for (int nt = 0; nt < 8; nt++)
                ldsm_x2(bfrag[nt], bs_b + 2u * ((nw * 64 + nt * 8 + (lane & 7)) * AS_LD +
                                                ((lane >> 3) & 1) * 8 + k0));
#pragma unroll
            for (int mt = 0; mt < 2; mt++)
#pragma unroll
                for (int nt = 0; nt < 8; nt++)
                    mma_f16(acc[mt][nt], afrag[mt], bfrag[nt]);
        }
    };

    load_g(0);
    sts(0);
    __syncthreads();

#pragma unroll 1
    for (int kt = 0; kt < 8; kt++) {
        const int buf = kt & 1;
        if (kt < 7) load_g(kt + 1);
        compute(buf);
        if (kt < 7) sts(buf ^ 1);
        __syncthreads();
    }

    // epilogue: acc -> g_hh (fp16 packed pairs)
#pragma unroll
    for (int mt = 0; mt < 2; mt++) {
        const int m0 = bm + mw * 32 + mt * 16 + (lane >> 2);
#pragma unroll
        for (int nt = 0; nt < 8; nt++) {
            const int n = bn + nw * 64 + nt * 8 + (lane & 3) * 2;
            __half2 p01 = __floats2half2_rn(acc[mt][nt][0], acc[mt][nt][1]);
            __half2 p23 = __floats2half2_rn(acc[mt][nt][2], acc[mt][nt][3]);
            if (m0 < M_NODES)
                *reinterpret_cast<__half2*>(&g_hh[(size_t)m0 * DCH + n]) = p01;
            if (m0 + 8 < M_NODES)
                *reinterpret_cast<__half2*>(&g_hh[(size_t)(m0 + 8) * DCH + n]) = p23;
        }
    }
}

// ===================== gather: 4 ch/thread, 2 nodes/block (R11 proven) =======
#define CE2(arr, a, b) { __half2 _mn = __hmin2(arr[a], arr[b]); \
                         __half2 _mx = __hmax2(arr[a], arr[b]); \
                         arr[a] = _mn; arr[b] = _mx; }

#define OEMS16(arr, o) \
    CE2(arr,o+0,o+1)  CE2(arr,o+2,o+3)   CE2(arr,o+4,o+5)   CE2(arr,o+6,o+7) \
    CE2(arr,o+8,o+9)  CE2(arr,o+10,o+11) CE2(arr,o+12,o+13) CE2(arr,o+14,o+15) \
    CE2(arr,o+0,o+2)  CE2(arr,o+1,o+3)   CE2(arr,o+4,o+6)   CE2(arr,o+5,o+7) \
    CE2(arr,o+8,o+10) CE2(arr,o+9,o+11)  CE2(arr,o+12,o+14) CE2(arr,o+13,o+15) \
    CE2(arr,o+1,o+2)  CE2(arr,o+5,o+6)   CE2(arr,o+9,o+10)  CE2(arr,o+13,o+14) \
    CE2(arr,o+0,o+4)  CE2(arr,o+1,o+5)   CE2(arr,o+2,o+6)   CE2(arr,o+3,o+7) \
    CE2(arr,o+8,o+12) CE2(arr,o+9,o+13)  CE2(arr,o+10,o+14) CE2(arr,o+11,o+15) \
    CE2(arr,o+2,o+4)  CE2(arr,o+3,o+5)   CE2(arr,o+10,o+12) CE2(arr,o+11,o+13) \
    CE2(arr,o+1,o+2)  CE2(arr,o+3,o+4)   CE2(arr,o+5,o+6) \
    CE2(arr,o+9,o+10) CE2(arr,o+11,o+12) CE2(arr,o+13,o+14) \
    CE2(arr,o+0,o+8)  CE2(arr,o+1,o+9)   CE2(arr,o+2,o+10)  CE2(arr,o+3,o+11) \
    CE2(arr,o+4,o+12) CE2(arr,o+5,o+13)  CE2(arr,o+6,o+14)  CE2(arr,o+7,o+15) \
    CE2(arr,o+4,o+8)  CE2(arr,o+5,o+9)   CE2(arr,o+6,o+10)  CE2(arr,o+7,o+11) \
    CE2(arr,o+2,o+4)  CE2(arr,o+3,o+5)   CE2(arr,o+6,o+8) \
    CE2(arr,o+7,o+9)  CE2(arr,o+10,o+12) CE2(arr,o+11,o+13) \
    CE2(arr,o+1,o+2)  CE2(arr,o+3,o+4)   CE2(arr,o+5,o+6)   CE2(arr,o+7,o+8) \
    CE2(arr,o+9,o+10) CE2(arr,o+11,o+12) CE2(arr,o+13,o+14)

#define SELECT32(arr) \
    OEMS16(arr, 0) \
    OEMS16(arr, 16) \
    _Pragma("unroll") \
    for (int i = 0; i < 16; i++) { \
        __half2 _a = arr[i], _b = arr[31 - i]; \
        arr[i]      = __hmin2(_a, _b); \
        arr[31 - i] = __hmax2(_a, _b); \
    } \
    _Pragma("unroll") \
    for (int j = 8; j >= 2; j >>= 1) \
        _Pragma("unroll") \
        for (int i = 0; i < j; i++) \
            arr[i] = __hmax2(arr[i], arr[i + j]); \
    _Pragma("unroll") \
    for (int j = 8; j >= 2; j >>= 1) \
        _Pragma("unroll") \
        for (int i = 0; i < j; i++) \
            arr[16 + i] = __hmin2(arr[16 + i], arr[16 + i + j]);

__global__ void __launch_bounds__(128) gather_trim(
    const void* __restrict__ nbrs_raw,
    float* __restrict__ out)
{
    __shared__ int sn[2][K_NBR];

    const int tid   = threadIdx.x;
    const int half  = tid >> 6;
    const int t64   = tid & 63;
    const int node  = blockIdx.x * 2 + half;

    if (tid < 2 * K_NBR) {
        const int  h = tid >> 5;
        const int  k = tid & 31;
        const int* w = reinterpret_cast<const int*>(nbrs_raw);
        unsigned m = __ballot_sync(0xffffffffu, w[2 * (tid & 31) + 1] == 0);
        bool is64 = (m == 0xffffffffu);
        long long nd = (long long)blockIdx.x * 2 + h;
        long long idx = is64
            ? reinterpret_cast<const long long*>(nbrs_raw)[nd * K_NBR + k]
            : (long long)reinterpret_cast<const int*>(nbrs_raw)[nd * K_NBR + k];
        sn[h][k] = (int)idx * DCH;
    }
    __syncthreads();

    __half2 va[K_NBR], vb[K_NBR];
#pragma unroll
    for (int k = 0; k < K_NBR; k++) {
        uint2 u = *reinterpret_cast<const uint2*>(&g_hh[sn[half][k] + 4 * t64]);
        va[k] = *reinterpret_cast<__half2*>(&u.x);
        vb[k] = *reinterpret_cast<__half2*>(&u.y);
    }

    SELECT32(va)
    SELECT32(vb)

    float2 a0 = __half22float2(va[0]),  a1 = __half22float2(va[1]);
    float2 a2 = __half22float2(va[16]), a3 = __half22float2(va[17]);
    float2 b0 = __half22float2(vb[0]),  b1 = __half22float2(vb[1]);
    float2 b2 = __half22float2(vb[16]), b3 = __half22float2(vb[17]);

    float4 r = make_float4((a0.x + a1.x + a2.x + a3.x) * 0.25f,
                           (a0.y + a1.y + a2.y + a3.y) * 0.25f,
                           (b0.x + b1.x + b2.x + b3.x) * 0.25f,
                           (b0.y + b1.y + b2.y + b3.y) * 0.25f);

    *reinterpret_cast<float4*>(&out[(size_t)node * DCH + 4 * t64]) = r;
}

// ===================== launch ===============================================
extern "C" void kernel_launch(void* const* d_in, const int* in_sizes, int n_in,
                              void* d_out, int out_size)
{
    const float* x    = nullptr;
    const void*  nbrs = nullptr;
    const float* W    = nullptr;

    for (int i = 0; i < n_in; i++) {
        if      (in_sizes[i] == M_NODES * DCH)   x    = (const float*)d_in[i];
        else if (in_sizes[i] == M_NODES * K_NBR) nbrs = d_in[i];
        else if (in_sizes[i] == DCH * DCH)       W    = (const float*)d_in[i];
    }
    if (!x)    x    = (const float*)d_in[0];
    if (!nbrs) nbrs = d_in[1];
    if (!W)    W    = (const float*)d_in[2];

    convert_w<<<(DCH * DCH / 4 + 255) / 256, 256>>>(W);

    dim3 ggrid((M_NODES + 127) / 128, 2);
    gemm_mma<<<ggrid, 256>>>(x);

    gather_trim<<<M_NODES / 2, 128>>>(nbrs, (float*)d_out);
}